// round 3
// baseline (speedup 1.0000x reference)
#include <cuda_runtime.h>
#include <cstdint>

#define N_PRE    50000
#define VEC_DIM  300        // 75 float4
#define HIDDEN   128        // 32 float4
#define IN_SIZE  50000      // VOCAB - N_PRE
#define OUT_DIM  428        // 107 float4
#define N_TOKENS (64 * 200) // 12800
#define TOK_PER_BLOCK 4     // one warp per token

// Warp-per-token. Each lane:
//   pre path: 3 independent float4 loads (lane, lane+32, lane+64<75) -> 3 stores,
//             plus bias float4 store -> MLP=3 on the latency-critical path.
//   oov path: 4 independent scalar W gathers (rows 4L..4L+3, column c) fused with
//             bias float4 -> 1 float4 store; zeros for the vector part.
__global__ __launch_bounds__(128) void encoder_kernel(
    const int*    __restrict__ tokens,    // [N_TOKENS]
    const float4* __restrict__ vectors4,  // [N_PRE * 75]
    const float*  __restrict__ W,         // [HIDDEN, IN_SIZE] row-major
    const float4* __restrict__ b4,        // [32] (HIDDEN floats)
    float4*       __restrict__ out4)      // [N_TOKENS * 107]
{
    const int lane = threadIdx.x & 31;
    const int warp = threadIdx.x >> 5;
    const int t    = blockIdx.x * TOK_PER_BLOCK + warp;

    const int tok = __ldg(&tokens[t]);          // broadcast, one sector
    float4* orow = out4 + (size_t)t * (OUT_DIM / 4);

    if (tok < N_PRE) {
        const float4* vrow = vectors4 + (size_t)tok * (VEC_DIM / 4);
        // issue all independent loads first (MLP=3 + bias)
        float4 v0 = __ldg(&vrow[lane]);
        float4 v1 = __ldg(&vrow[lane + 32]);
        float4 v2;
        const bool has2 = (lane + 64) < 75;     // 11 lanes
        if (has2) v2 = __ldg(&vrow[lane + 64]);
        float4 bb = __ldg(&b4[lane]);

        orow[lane]      = v0;
        orow[lane + 32] = v1;
        if (has2) orow[lane + 64] = v2;
        orow[75 + lane] = bb;                   // hidden part = bias
    } else {
        const int c = tok - N_PRE;              // 0 <= c < IN_SIZE
        // 4 independent column-gather loads: rows 4*lane .. 4*lane+3
        const float* Wc = W + c;
        const size_t r0 = (size_t)(4 * lane) * IN_SIZE;
        float w0 = __ldg(Wc + r0);
        float w1 = __ldg(Wc + r0 + (size_t)IN_SIZE);
        float w2 = __ldg(Wc + r0 + (size_t)2 * IN_SIZE);
        float w3 = __ldg(Wc + r0 + (size_t)3 * IN_SIZE);
        float4 bb = __ldg(&b4[lane]);

        // vector part: zeros (3 float4 stores per lane)
        const float4 z = make_float4(0.f, 0.f, 0.f, 0.f);
        orow[lane]      = z;
        orow[lane + 32] = z;
        if ((lane + 64) < 75) orow[lane + 64] = z;

        // hidden part: b + W[:, c], one vectorized store per lane
        float4 h;
        h.x = bb.x + w0;
        h.y = bb.y + w1;
        h.z = bb.z + w2;
        h.w = bb.w + w3;
        orow[75 + lane] = h;
    }
}

extern "C" void kernel_launch(void* const* d_in, const int* in_sizes, int n_in,
                              void* d_out, int out_size)
{
    // metadata order: tokens (int32), vectors (f32), W (f32), b (f32)
    const int*    tokens  = (const int*)   d_in[0];
    const float4* vectors = (const float4*)d_in[1];
    const float*  W       = (const float*) d_in[2];
    const float4* b       = (const float4*)d_in[3];
    float4*       out     = (float4*)      d_out;

    encoder_kernel<<<N_TOKENS / TOK_PER_BLOCK, 128>>>(tokens, vectors, W, b, out);
}